// round 1
// baseline (speedup 1.0000x reference)
#include <cuda_runtime.h>
#include <cuda_bf16.h>

// Problem constants (shapes are fixed for this problem instance)
#define NMAX   50000
#define EMAX   800000
#define GRAPHS 256
#define HC     256      // H*C
#define KIN    300      // n_in
#define FOUT   768      // nout

// ---------------- scratch (device globals; no allocation) ----------------
__device__ float g_h[NMAX * HC];            // node features after linear  [N,256]
__device__ float g_asrc[NMAX * 4];          // per-node src attention logits [N,4]
__device__ float g_adst[NMAX * 4];          // per-node dst attention logits [N,4]
__device__ float g_emax[NMAX * 4];          // segment max per dst node     [N,4]
__device__ float g_denom[NMAX * 4];         // segment sum of exp           [N,4]
__device__ float g_e[(EMAX + NMAX) * 4];    // per-edge logits -> exp       [E+N,4]
__device__ float g_out[NMAX * HC];          // aggregated output            [N,256]
__device__ float g_pool[GRAPHS * HC];       // per-graph sums               [G,256]
__device__ float g_cnt[GRAPHS];             // per-graph node counts

// ---------------- helpers ----------------
__device__ __forceinline__ void atomicMaxF(float* addr, float v) {
    if (v >= 0.0f) {
        atomicMax((int*)addr, __float_as_int(v));
    } else {
        atomicMin((unsigned int*)addr, __float_as_uint(v));
    }
}

// ---------------- 0: init scratch ----------------
__global__ void init_kernel(int M) {
    int i = blockIdx.x * blockDim.x + threadIdx.x;
    if (i < M * HC)     g_out[i]  = 0.0f;
    if (i < M * 4)    { g_denom[i] = 0.0f; g_emax[i] = -1e30f; }
    if (i < GRAPHS * HC) g_pool[i] = 0.0f;
    if (i < GRAPHS)      g_cnt[i]  = 0.0f;
}

// ---------------- 1: h = x @ lin_w  (+ fused att-logit dots) ----------------
// Block = 64 rows x 64 cols; the 64-col tile is exactly one head, so the
// per-row dot with att_src/att_dst for that head reduces entirely within the block.
#define BM 64
#define BN 64
#define BK 16
__global__ void gemm_h_kernel(const float* __restrict__ X,
                              const float* __restrict__ W,
                              const float* __restrict__ att_s,
                              const float* __restrict__ att_d,
                              int M) {
    __shared__ float As[BK][BM];
    __shared__ float Bs[BK][BN];
    __shared__ float s_as[BN], s_ad[BN];

    const int head = blockIdx.x;          // 0..3 -> cols [head*64, head*64+64)
    const int row0 = blockIdx.y * BM;
    const int tid  = threadIdx.x;         // 256 threads
    const int tx   = tid & 15;
    const int ty   = tid >> 4;

    if (tid < BN) { s_as[tid] = att_s[head * 64 + tid]; s_ad[tid] = att_d[head * 64 + tid]; }

    float acc[4][4];
#pragma unroll
    for (int i = 0; i < 4; i++)
#pragma unroll
        for (int j = 0; j < 4; j++) acc[i][j] = 0.0f;

    for (int k0 = 0; k0 < KIN; k0 += BK) {
        // load A tile (64x16), transposed into As[k][m]
#pragma unroll
        for (int i = tid; i < BM * BK; i += 256) {
            int m = i >> 4, kk = i & 15;
            int gr = row0 + m, gk = k0 + kk;
            As[kk][m] = (gr < M && gk < KIN) ? X[gr * KIN + gk] : 0.0f;
        }
        // load B tile (16x64)
#pragma unroll
        for (int i = tid; i < BK * BN; i += 256) {
            int kk = i >> 6, nn = i & 63;
            int gk = k0 + kk;
            Bs[kk][nn] = (gk < KIN) ? W[gk * HC + head * 64 + nn] : 0.0f;
        }
        __syncthreads();
#pragma unroll
        for (int kk = 0; kk < BK; kk++) {
            float4 a4 = *(const float4*)&As[kk][ty * 4];
            float4 b4 = *(const float4*)&Bs[kk][tx * 4];
            float a[4] = {a4.x, a4.y, a4.z, a4.w};
            float b[4] = {b4.x, b4.y, b4.z, b4.w};
#pragma unroll
            for (int i = 0; i < 4; i++)
#pragma unroll
                for (int j = 0; j < 4; j++) acc[i][j] += a[i] * b[j];
        }
        __syncthreads();
    }

    // epilogue: write h, and reduce per-row att dots across the 16 tx lanes
#pragma unroll
    for (int i = 0; i < 4; i++) {
        int gr = row0 + ty * 4 + i;
        bool ok = gr < M;
        float s = 0.0f, d = 0.0f;
#pragma unroll
        for (int j = 0; j < 4; j++) {
            if (ok) g_h[gr * HC + head * 64 + tx * 4 + j] = acc[i][j];
            s += acc[i][j] * s_as[tx * 4 + j];
            d += acc[i][j] * s_ad[tx * 4 + j];
        }
#pragma unroll
        for (int off = 8; off > 0; off >>= 1) {
            s += __shfl_down_sync(0xffffffffu, s, off, 16);
            d += __shfl_down_sync(0xffffffffu, d, off, 16);
        }
        if (ok && tx == 0) {
            g_asrc[gr * 4 + head] = s;
            g_adst[gr * 4 + head] = d;
        }
    }
}

// ---------------- 2: per-edge logits + segment max ----------------
__global__ void edge_logit_kernel(const int* __restrict__ ei, int E, int M) {
    int i = blockIdx.x * blockDim.x + threadIdx.x;
    int total = E + M;
    if (i >= total) return;
    int s, d;
    if (i < E) { s = ei[i]; d = ei[E + i]; }
    else       { s = d = i - E; }
    float4 as = ((const float4*)g_asrc)[s];
    float4 ad = ((const float4*)g_adst)[d];
    float e0 = as.x + ad.x, e1 = as.y + ad.y, e2 = as.z + ad.z, e3 = as.w + ad.w;
    e0 = e0 > 0.f ? e0 : 0.2f * e0;
    e1 = e1 > 0.f ? e1 : 0.2f * e1;
    e2 = e2 > 0.f ? e2 : 0.2f * e2;
    e3 = e3 > 0.f ? e3 : 0.2f * e3;
    ((float4*)g_e)[i] = make_float4(e0, e1, e2, e3);
    atomicMaxF(&g_emax[d * 4 + 0], e0);
    atomicMaxF(&g_emax[d * 4 + 1], e1);
    atomicMaxF(&g_emax[d * 4 + 2], e2);
    atomicMaxF(&g_emax[d * 4 + 3], e3);
}

// ---------------- 3: exp + segment sum ----------------
__global__ void edge_exp_kernel(const int* __restrict__ ei, int E, int M) {
    int i = blockIdx.x * blockDim.x + threadIdx.x;
    int total = E + M;
    if (i >= total) return;
    int d = (i < E) ? ei[E + i] : (i - E);
    float4 e4 = ((const float4*)g_e)[i];
    float4 mx = ((const float4*)g_emax)[d];
    float4 ee = make_float4(__expf(e4.x - mx.x), __expf(e4.y - mx.y),
                            __expf(e4.z - mx.z), __expf(e4.w - mx.w));
    ((float4*)g_e)[i] = ee;
    atomicAdd(&g_denom[d * 4 + 0], ee.x);
    atomicAdd(&g_denom[d * 4 + 1], ee.y);
    atomicAdd(&g_denom[d * 4 + 2], ee.z);
    atomicAdd(&g_denom[d * 4 + 3], ee.w);
}

// ---------------- 4: weighted scatter (64 threads per edge) ----------------
__global__ void edge_scatter_kernel(const int* __restrict__ ei, int E, int M) {
    long long gtid = (long long)blockIdx.x * blockDim.x + threadIdx.x;
    int eid = (int)(gtid >> 6);
    int t   = (int)(gtid & 63);
    int total = E + M;
    if (eid >= total) return;
    int s, d;
    if (eid < E) { s = ei[eid]; d = ei[E + eid]; }
    else         { s = d = eid - E; }
    float4 ee = ((const float4*)g_e)[eid];
    float4 dn = ((const float4*)g_denom)[d];
    float a0 = ee.x / dn.x, a1 = ee.y / dn.y, a2 = ee.z / dn.z, a3 = ee.w / dn.w;
    const float* hs = &g_h[(long long)s * HC];
    float* od = &g_out[(long long)d * HC];
    atomicAdd(&od[0 * 64 + t], hs[0 * 64 + t] * a0);
    atomicAdd(&od[1 * 64 + t], hs[1 * 64 + t] * a1);
    atomicAdd(&od[2 * 64 + t], hs[2 * 64 + t] * a2);
    atomicAdd(&od[3 * 64 + t], hs[3 * 64 + t] * a3);
}

// ---------------- 5: bias + leaky + pooled sums ----------------
__global__ void node_pool_kernel(const int* __restrict__ batch,
                                 const float* __restrict__ bias, int M) {
    int idx = blockIdx.x * blockDim.x + threadIdx.x;
    if (idx >= M * HC) return;
    int n = idx >> 8;
    int c = idx & 255;
    float v = g_out[idx] + bias[c];
    v = v > 0.f ? v : 0.01f * v;
    int b = batch[n];
    atomicAdd(&g_pool[b * HC + c], v);
    if (c == 0) atomicAdd(&g_cnt[b], 1.0f);
}

// ---------------- 6: mean + final FC ----------------
__global__ void final_fc_kernel(const float* __restrict__ fc1_w,
                                const float* __restrict__ fc1_b,
                                float* __restrict__ out) {
    __shared__ float p[HC];
    int g = blockIdx.x;
    int tid = threadIdx.x;   // 256
    float inv = 1.0f / fmaxf(g_cnt[g], 1.0f);
    p[tid] = g_pool[g * HC + tid] * inv;
    __syncthreads();
#pragma unroll
    for (int j0 = 0; j0 < FOUT; j0 += 256) {
        int j = j0 + tid;
        float acc = fc1_b[j];
#pragma unroll 8
        for (int k = 0; k < HC; k++) acc += p[k] * fc1_w[k * FOUT + j];
        out[g * FOUT + j] = acc;
    }
}

// ---------------- launch ----------------
extern "C" void kernel_launch(void* const* d_in, const int* in_sizes, int n_in,
                              void* d_out, int out_size) {
    const float* x     = (const float*)d_in[0];
    const int*   ei    = (const int*)d_in[1];
    const int*   batch = (const int*)d_in[2];
    const float* lin_w = (const float*)d_in[3];
    const float* att_s = (const float*)d_in[4];
    const float* att_d = (const float*)d_in[5];
    const float* bias  = (const float*)d_in[6];
    const float* fc1_w = (const float*)d_in[7];
    const float* fc1_b = (const float*)d_in[8];
    float* out = (float*)d_out;

    int M = in_sizes[2];       // number of nodes
    int E = in_sizes[1] / 2;   // number of edges

    int initN = M * HC;
    init_kernel<<<(initN + 255) / 256, 256>>>(M);

    dim3 ggrid(4, (M + BM - 1) / BM);
    gemm_h_kernel<<<ggrid, 256>>>(x, lin_w, att_s, att_d, M);

    int total = E + M;
    edge_logit_kernel<<<(total + 255) / 256, 256>>>(ei, E, M);
    edge_exp_kernel<<<(total + 255) / 256, 256>>>(ei, E, M);

    long long scatterThreads = (long long)total * 64;
    edge_scatter_kernel<<<(unsigned)((scatterThreads + 255) / 256), 256>>>(ei, E, M);

    node_pool_kernel<<<(M * HC + 255) / 256, 256>>>(batch, bias, M);

    final_fc_kernel<<<GRAPHS, 256>>>(fc1_w, fc1_b, out);
}

// round 2
// speedup vs baseline: 2.0948x; 2.0948x over previous
#include <cuda_runtime.h>
#include <cuda_bf16.h>

// Problem constants
#define NMAX   50000
#define EMAX   800000
#define TOTMAX (EMAX + NMAX)
#define GRAPHS 256
#define HC     256      // H*C
#define KIN    300      // n_in
#define FOUT   768      // nout

// ---------------- scratch (device globals; no allocation) ----------------
__device__ float  g_h[NMAX * HC];          // node features after linear [N,256]
__device__ float  g_asrc[NMAX * 4];        // per-node src attention logits [N,4]
__device__ float  g_adst[NMAX * 4];        // per-node dst attention logits [N,4]
__device__ float  g_emax[NMAX * 4];        // segment max per dst node [N,4]
__device__ float  g_denom[NMAX * 4];       // segment sum of exp [N,4]
__device__ float  g_e[TOTMAX * 4];         // per-edge leaky logits [E+N,4]
__device__ int    g_count[NMAX];           // in-degree (incl self-loop)
__device__ int    g_scanex[NMAX];          // per-chunk exclusive scan
__device__ int    g_bsum[64];              // chunk totals -> chunk offsets
__device__ int    g_rowoff[NMAX];          // CSR row offsets
__device__ int    g_cursor[NMAX];          // fill cursors
__device__ int    g_csrc[TOTMAX];          // CSR-ordered src ids
__device__ float4 g_cee[TOTMAX];           // CSR-ordered exp weights (per head)
__device__ float  g_pool[GRAPHS * HC];     // per-graph sums [G,256]
__device__ float  g_cnt[GRAPHS];           // per-graph node counts

// ---------------- helpers ----------------
__device__ __forceinline__ void atomicMaxF(float* addr, float v) {
    if (v >= 0.0f) atomicMax((int*)addr, __float_as_int(v));
    else           atomicMin((unsigned int*)addr, __float_as_uint(v));
}

// ---------------- 0: init scratch ----------------
__global__ void init_kernel(int M) {
    int i = blockIdx.x * blockDim.x + threadIdx.x;
    if (i < M * 4)      { g_denom[i] = 0.0f; g_emax[i] = -1e30f; }
    if (i < M)            g_count[i] = 0;
    if (i < GRAPHS * HC)  g_pool[i]  = 0.0f;
    if (i < GRAPHS)       g_cnt[i]   = 0.0f;
}

// ---------------- 1: h = x @ lin_w (+ fused attention dots) ----------------
// 128x128 tile, BK=8, 256 threads, 8x8 per thread (2x2 blocks of 4x4).
#define BM 128
#define BN 128
#define BK 8
__global__ __launch_bounds__(256, 2)
void gemm_h_kernel(const float* __restrict__ X,
                   const float* __restrict__ W,
                   const float* __restrict__ att_s,
                   const float* __restrict__ att_d,
                   int M) {
    __shared__ float As[BK][BM];
    __shared__ float Bs[BK][BN];
    __shared__ float s_as[BN], s_ad[BN];

    const int bx   = blockIdx.x;              // 0..1 -> N offset bx*128 (heads bx*2, bx*2+1)
    const int row0 = blockIdx.y * BM;
    const int tid  = threadIdx.x;
    const int tx   = tid & 15;
    const int ty   = tid >> 4;

    if (tid < BN) { s_as[tid] = att_s[bx * BN + tid]; s_ad[tid] = att_d[bx * BN + tid]; }

    float acc[2][2][4][4];
#pragma unroll
    for (int a = 0; a < 2; a++)
#pragma unroll
        for (int b = 0; b < 2; b++)
#pragma unroll
            for (int i = 0; i < 4; i++)
#pragma unroll
                for (int j = 0; j < 4; j++) acc[a][b][i][j] = 0.0f;

    const int arow  = tid >> 1;             // 0..127
    const int akb   = (tid & 1) * 4;        // 0 or 4
    const int bkk   = tid >> 5;             // 0..7
    const int bcol  = (tid & 31) * 4;       // 0..124

    for (int k0 = 0; k0 < KIN; k0 += BK) {
        // A tile: 128 rows x 8 k, transposed. 1 float4 per thread.
        {
            int gr = row0 + arow, gk = k0 + akb;
            float4 a4 = make_float4(0.f, 0.f, 0.f, 0.f);
            if (gr < M && gk < KIN) a4 = *(const float4*)&X[gr * KIN + gk];
            As[akb + 0][arow] = a4.x;
            As[akb + 1][arow] = a4.y;
            As[akb + 2][arow] = a4.z;
            As[akb + 3][arow] = a4.w;
        }
        // B tile: 8 k x 128 cols. 1 float4 per thread.
        {
            int gk = k0 + bkk;
            float4 b4 = make_float4(0.f, 0.f, 0.f, 0.f);
            if (gk < KIN) b4 = *(const float4*)&W[gk * HC + bx * BN + bcol];
            *(float4*)&Bs[bkk][bcol] = b4;
        }
        __syncthreads();
#pragma unroll
        for (int kk = 0; kk < BK; kk++) {
            float4 a0 = *(const float4*)&As[kk][ty * 4];
            float4 a1 = *(const float4*)&As[kk][64 + ty * 4];
            float4 b0 = *(const float4*)&Bs[kk][tx * 4];
            float4 b1 = *(const float4*)&Bs[kk][64 + tx * 4];
            float av[2][4] = {{a0.x, a0.y, a0.z, a0.w}, {a1.x, a1.y, a1.z, a1.w}};
            float bv[2][4] = {{b0.x, b0.y, b0.z, b0.w}, {b1.x, b1.y, b1.z, b1.w}};
#pragma unroll
            for (int a = 0; a < 2; a++)
#pragma unroll
                for (int b = 0; b < 2; b++)
#pragma unroll
                    for (int i = 0; i < 4; i++)
#pragma unroll
                        for (int j = 0; j < 4; j++)
                            acc[a][b][i][j] += av[a][i] * bv[b][j];
        }
        __syncthreads();
    }

    // epilogue: store h + fused attention dots
#pragma unroll
    for (int a = 0; a < 2; a++) {
#pragma unroll
        for (int i = 0; i < 4; i++) {
            int gr = row0 + a * 64 + ty * 4 + i;
            bool ok = gr < M;
#pragma unroll
            for (int b = 0; b < 2; b++) {
                if (ok) {
                    *(float4*)&g_h[gr * HC + bx * BN + b * 64 + tx * 4] =
                        make_float4(acc[a][b][i][0], acc[a][b][i][1],
                                    acc[a][b][i][2], acc[a][b][i][3]);
                }
                // attention dot for head (bx*2 + b) over this thread's 4 cols
                float s = 0.f, d = 0.f;
#pragma unroll
                for (int j = 0; j < 4; j++) {
                    s += acc[a][b][i][j] * s_as[b * 64 + tx * 4 + j];
                    d += acc[a][b][i][j] * s_ad[b * 64 + tx * 4 + j];
                }
#pragma unroll
                for (int off = 8; off > 0; off >>= 1) {
                    s += __shfl_down_sync(0xffffffffu, s, off, 16);
                    d += __shfl_down_sync(0xffffffffu, d, off, 16);
                }
                if (ok && tx == 0) {
                    g_asrc[gr * 4 + bx * 2 + b] = s;
                    g_adst[gr * 4 + bx * 2 + b] = d;
                }
            }
        }
    }
}

// ---------------- 2: per-edge logits + segment max + degree count ----------------
__global__ void edge_logit_kernel(const int* __restrict__ ei, int E, int M) {
    int i = blockIdx.x * blockDim.x + threadIdx.x;
    int total = E + M;
    if (i >= total) return;
    int s, d;
    if (i < E) { s = ei[i]; d = ei[E + i]; }
    else       { s = d = i - E; }
    float4 as = ((const float4*)g_asrc)[s];
    float4 ad = ((const float4*)g_adst)[d];
    float e0 = as.x + ad.x, e1 = as.y + ad.y, e2 = as.z + ad.z, e3 = as.w + ad.w;
    e0 = e0 > 0.f ? e0 : 0.2f * e0;
    e1 = e1 > 0.f ? e1 : 0.2f * e1;
    e2 = e2 > 0.f ? e2 : 0.2f * e2;
    e3 = e3 > 0.f ? e3 : 0.2f * e3;
    ((float4*)g_e)[i] = make_float4(e0, e1, e2, e3);
    atomicMaxF(&g_emax[d * 4 + 0], e0);
    atomicMaxF(&g_emax[d * 4 + 1], e1);
    atomicMaxF(&g_emax[d * 4 + 2], e2);
    atomicMaxF(&g_emax[d * 4 + 3], e3);
    atomicAdd(&g_count[d], 1);
}

// ---------------- 3: 2-level exclusive scan of g_count ----------------
__global__ void scan1_kernel(int M) {                     // block=1024
    __shared__ int sh[2][1024];
    int i = blockIdx.x * 1024 + threadIdx.x;
    int v = (i < M) ? g_count[i] : 0;
    int buf = 0;
    sh[0][threadIdx.x] = v;
    __syncthreads();
#pragma unroll
    for (int off = 1; off < 1024; off <<= 1) {
        int nv = sh[buf][threadIdx.x];
        if (threadIdx.x >= off) nv += sh[buf][threadIdx.x - off];
        sh[1 - buf][threadIdx.x] = nv;
        buf = 1 - buf;
        __syncthreads();
    }
    int incl = sh[buf][threadIdx.x];
    if (i < M) g_scanex[i] = incl - v;
    if (threadIdx.x == 1023) g_bsum[blockIdx.x] = incl;
}

__global__ void scan2_kernel(int nb) {                    // 1 thread
    int run = 0;
    for (int b = 0; b < nb; b++) { int t = g_bsum[b]; g_bsum[b] = run; run += t; }
}

__global__ void scan3_kernel(int M) {
    int i = blockIdx.x * blockDim.x + threadIdx.x;
    if (i >= M) return;
    int off = g_scanex[i] + g_bsum[i >> 10];
    g_rowoff[i] = off;
    g_cursor[i] = off;
}

// ---------------- 4: exp + segment sum + CSR fill ----------------
__global__ void edge_exp_fill_kernel(const int* __restrict__ ei, int E, int M) {
    int i = blockIdx.x * blockDim.x + threadIdx.x;
    int total = E + M;
    if (i >= total) return;
    int s, d;
    if (i < E) { s = ei[i]; d = ei[E + i]; }
    else       { s = d = i - E; }
    float4 e4 = ((const float4*)g_e)[i];
    float4 mx = ((const float4*)g_emax)[d];
    float4 ee = make_float4(__expf(e4.x - mx.x), __expf(e4.y - mx.y),
                            __expf(e4.z - mx.z), __expf(e4.w - mx.w));
    int pos = atomicAdd(&g_cursor[d], 1);
    g_csrc[pos] = s;
    g_cee[pos]  = ee;
    atomicAdd(&g_denom[d * 4 + 0], ee.x);
    atomicAdd(&g_denom[d * 4 + 1], ee.y);
    atomicAdd(&g_denom[d * 4 + 2], ee.z);
    atomicAdd(&g_denom[d * 4 + 3], ee.w);
}

// ---------------- 5: gather-aggregate (warp per node) + bias + leaky + pool ----------------
__global__ void aggregate_kernel(const int* __restrict__ batch,
                                 const float* __restrict__ bias, int M) {
    int w = blockIdx.x * (blockDim.x >> 5) + (threadIdx.x >> 5);
    if (w >= M) return;
    int lane = threadIdx.x & 31;
    int start = g_rowoff[w];
    int end   = start + g_count[w];
    int hsel  = lane >> 3;                      // head for this thread's 8 channels

    float acc[8];
#pragma unroll
    for (int k = 0; k < 8; k++) acc[k] = 0.0f;

    int src = 0; float4 ee = make_float4(0, 0, 0, 0);
    if (start < end) { src = g_csrc[start]; ee = g_cee[start]; }
    for (int j = start; j < end; j++) {
        int nsrc = 0; float4 nee = ee;
        if (j + 1 < end) { nsrc = g_csrc[j + 1]; nee = g_cee[j + 1]; }
        const float4* hp = (const float4*)&g_h[(long long)src * HC + lane * 8];
        float4 h0 = hp[0], h1 = hp[1];
        float wgt = ((const float*)&ee)[hsel];
        acc[0] += h0.x * wgt; acc[1] += h0.y * wgt;
        acc[2] += h0.z * wgt; acc[3] += h0.w * wgt;
        acc[4] += h1.x * wgt; acc[5] += h1.y * wgt;
        acc[6] += h1.z * wgt; acc[7] += h1.w * wgt;
        src = nsrc; ee = nee;
    }

    float4 dn = ((const float4*)g_denom)[w];
    float inv = 1.0f / ((const float*)&dn)[hsel];
    int b = batch[w];
    float* pp = &g_pool[b * HC + lane * 8];
#pragma unroll
    for (int k = 0; k < 8; k++) {
        float v = acc[k] * inv + bias[lane * 8 + k];
        v = v > 0.f ? v : 0.01f * v;
        atomicAdd(&pp[k], v);
    }
    if (lane == 0) atomicAdd(&g_cnt[b], 1.0f);
}

// ---------------- 6: mean + final FC ----------------
__global__ void final_fc_kernel(const float* __restrict__ fc1_w,
                                const float* __restrict__ fc1_b,
                                float* __restrict__ out) {
    __shared__ float p[HC];
    int g = blockIdx.x;
    int tid = threadIdx.x;   // 256
    float inv = 1.0f / fmaxf(g_cnt[g], 1.0f);
    p[tid] = g_pool[g * HC + tid] * inv;
    __syncthreads();
#pragma unroll
    for (int j0 = 0; j0 < FOUT; j0 += 256) {
        int j = j0 + tid;
        float acc = fc1_b[j];
#pragma unroll 8
        for (int k = 0; k < HC; k++) acc += p[k] * fc1_w[k * FOUT + j];
        out[g * FOUT + j] = acc;
    }
}

// ---------------- launch ----------------
extern "C" void kernel_launch(void* const* d_in, const int* in_sizes, int n_in,
                              void* d_out, int out_size) {
    const float* x     = (const float*)d_in[0];
    const int*   ei    = (const int*)d_in[1];
    const int*   batch = (const int*)d_in[2];
    const float* lin_w = (const float*)d_in[3];
    const float* att_s = (const float*)d_in[4];
    const float* att_d = (const float*)d_in[5];
    const float* bias  = (const float*)d_in[6];
    const float* fc1_w = (const float*)d_in[7];
    const float* fc1_b = (const float*)d_in[8];
    float* out = (float*)d_out;

    int M = in_sizes[2];       // nodes
    int E = in_sizes[1] / 2;   // edges
    int total = E + M;

    int initN = M * 4 > GRAPHS * HC ? M * 4 : GRAPHS * HC;
    init_kernel<<<(initN + 255) / 256, 256>>>(M);

    dim3 ggrid(2, (M + BM - 1) / BM);
    gemm_h_kernel<<<ggrid, 256>>>(x, lin_w, att_s, att_d, M);

    edge_logit_kernel<<<(total + 255) / 256, 256>>>(ei, E, M);

    int nb = (M + 1023) / 1024;
    scan1_kernel<<<nb, 1024>>>(M);
    scan2_kernel<<<1, 1>>>(nb);
    scan3_kernel<<<(M + 255) / 256, 256>>>(M);

    edge_exp_fill_kernel<<<(total + 255) / 256, 256>>>(ei, E, M);

    aggregate_kernel<<<(M * 32 + 255) / 256, 256>>>(batch, bias, M);

    final_fc_kernel<<<GRAPHS, 256>>>(fc1_w, fc1_b, out);
}